// round 10
// baseline (speedup 1.0000x reference)
#include <cuda_runtime.h>
#include <cuda_bf16.h>
#include <cstdint>

// Problem constants
#define TT 512
#define BB 64
#define II 256
#define HH 1024
#define OO 256
#define OUT_ELEMS   (TT * BB * OO)

// ---------------- recurrent kernel configuration (HMMA mma.sync path) ------
#define REC_CTAS    64            // 32 j-slices x 2 b-halves
#define REC_THREADS 256
#define NCHUNK      8             // K=1024 in chunks of 128
#define CHUNK_K     128

// smem layout (bytes, dynamic)
// wT: bf16 [2 mats][32 n][1032 k-padded]  (uint32 stride 516, 516%32==4)
#define SM_WT       0
#define WT_MAT_B    (32 * 516 * 4)            // 66048
// hbuf: bf16 [2 bufs][2 mats][32 rows][136 k-padded] (uint32 stride 68)
#define SM_HB       (2 * WT_MAT_B)            // 132096
#define HB_BUF_B    (2 * 32 * 68 * 4)         // 17408 per buf (hi+lo)
#define HB_MAT_B    (32 * 68 * 4)             // 8704
// red: f32 [8 warps][16 rows][40 cols-padded]
#define SM_RED      (SM_HB + 2 * HB_BUF_B)    // 166912
#define RED_W       640                       // words per warp (16*40)
#define REC_SMEM_BYTES (SM_RED + 8 * 16 * 40 * 4)   // 187392

// Scratch (device globals: no cudaMalloc allowed)
__device__ float g_pre[TT * BB * HH];
__device__ __align__(16) __nv_bfloat16 g_hx_hi[2][BB * HH];
__device__ __align__(16) __nv_bfloat16 g_hx_lo[2][BB * HH];
__device__ unsigned g_arrived = 0;
__device__ unsigned g_flags[REC_CTAS][32];    // one 128B line per CTA

__device__ __forceinline__ void grid_sync() {
    __syncthreads();
    if (threadIdx.x == 0) {
        __threadfence();
        unsigned ticket = atomicAdd(&g_arrived, 1u) + 1u;
        unsigned target = ((ticket + (REC_CTAS - 1u)) / REC_CTAS) * REC_CTAS;
        unsigned cur;
        do {
            asm volatile("ld.acquire.gpu.global.u32 %0, [%1];"
                         : "=r"(cur) : "l"(&g_arrived) : "memory");
        } while ((int)(cur - target) < 0);
        __threadfence();
    }
    __syncthreads();
}

__device__ __forceinline__ void mma16816(float* d, uint32_t a0, uint32_t a1,
                                         uint32_t a2, uint32_t a3,
                                         uint32_t b0, uint32_t b1) {
    asm volatile(
        "mma.sync.aligned.m16n8k16.row.col.f32.bf16.bf16.f32 "
        "{%0,%1,%2,%3}, {%4,%5,%6,%7}, {%8,%9}, {%0,%1,%2,%3};"
        : "+f"(d[0]), "+f"(d[1]), "+f"(d[2]), "+f"(d[3])
        : "r"(a0), "r"(a1), "r"(a2), "r"(a3), "r"(b0), "r"(b1));
}

// ---------------------------------------------------------------------------
// Generic fp32 GEMM:  C[M,N] = A[M,K] @ B[N,K]^T + bias[N]   (unchanged;
// measured at the fp32 SIMT roofline)
// ---------------------------------------------------------------------------
__global__ void __launch_bounds__(256) gemm_tn_kernel(
    const float* __restrict__ A, const float* __restrict__ B,
    const float* __restrict__ bias, float* __restrict__ C,
    int M, int N, int K)
{
    __shared__ float Ast[32][68];
    __shared__ float Bst[32][68];

    const int tid   = threadIdx.x;
    const int mBase = blockIdx.x * 64;
    const int nBase = blockIdx.y * 64;
    const int lrow  = tid >> 3;
    const int lk    = (tid & 7) << 2;
    const int tx    = tid & 15;
    const int ty    = tid >> 4;

    float acc[4][4] = {};

    const float* Ap = A + (size_t)(mBase + lrow) * K + lk;
    const float* Bp = B + (size_t)(nBase + lrow) * K + lk;

    for (int k0 = 0; k0 < K; k0 += 32) {
        float4 av0 = *(const float4*)(Ap + k0);
        float4 av1 = *(const float4*)(Ap + (size_t)32 * K + k0);
        float4 bv0 = *(const float4*)(Bp + k0);
        float4 bv1 = *(const float4*)(Bp + (size_t)32 * K + k0);
        __syncthreads();
        Ast[lk + 0][lrow] = av0.x; Ast[lk + 1][lrow] = av0.y;
        Ast[lk + 2][lrow] = av0.z; Ast[lk + 3][lrow] = av0.w;
        Ast[lk + 0][lrow + 32] = av1.x; Ast[lk + 1][lrow + 32] = av1.y;
        Ast[lk + 2][lrow + 32] = av1.z; Ast[lk + 3][lrow + 32] = av1.w;
        Bst[lk + 0][lrow] = bv0.x; Bst[lk + 1][lrow] = bv0.y;
        Bst[lk + 2][lrow] = bv0.z; Bst[lk + 3][lrow] = bv0.w;
        Bst[lk + 0][lrow + 32] = bv1.x; Bst[lk + 1][lrow + 32] = bv1.y;
        Bst[lk + 2][lrow + 32] = bv1.z; Bst[lk + 3][lrow + 32] = bv1.w;
        __syncthreads();
        #pragma unroll
        for (int k = 0; k < 32; k++) {
            float4 a = *(const float4*)&Ast[k][ty * 4];
            float4 b = *(const float4*)&Bst[k][tx * 4];
            acc[0][0] = fmaf(a.x, b.x, acc[0][0]);
            acc[0][1] = fmaf(a.x, b.y, acc[0][1]);
            acc[0][2] = fmaf(a.x, b.z, acc[0][2]);
            acc[0][3] = fmaf(a.x, b.w, acc[0][3]);
            acc[1][0] = fmaf(a.y, b.x, acc[1][0]);
            acc[1][1] = fmaf(a.y, b.y, acc[1][1]);
            acc[1][2] = fmaf(a.y, b.z, acc[1][2]);
            acc[1][3] = fmaf(a.y, b.w, acc[1][3]);
            acc[2][0] = fmaf(a.z, b.x, acc[2][0]);
            acc[2][1] = fmaf(a.z, b.y, acc[2][1]);
            acc[2][2] = fmaf(a.z, b.z, acc[2][2]);
            acc[2][3] = fmaf(a.z, b.w, acc[2][3]);
            acc[3][0] = fmaf(a.w, b.x, acc[3][0]);
            acc[3][1] = fmaf(a.w, b.y, acc[3][1]);
            acc[3][2] = fmaf(a.w, b.z, acc[3][2]);
            acc[3][3] = fmaf(a.w, b.w, acc[3][3]);
        }
    }

    const float b0 = bias[nBase + tx * 4 + 0];
    const float b1 = bias[nBase + tx * 4 + 1];
    const float b2 = bias[nBase + tx * 4 + 2];
    const float b3 = bias[nBase + tx * 4 + 3];
    #pragma unroll
    for (int i = 0; i < 4; i++) {
        float4 o;
        o.x = acc[i][0] + b0; o.y = acc[i][1] + b1;
        o.z = acc[i][2] + b2; o.w = acc[i][3] + b3;
        *(float4*)&C[(size_t)(mBase + ty * 4 + i) * N + nBase + tx * 4] = o;
    }
}

// ---------------------------------------------------------------------------
// HMMA persistent recurrence: h_t = tanh(pre_t + h_{t-1} @ wR), 512 steps.
// CTA (bs = bx>>5, jt = bx&31): D[32 b-rows of half bs][32 j of slice jt].
// Warp w = mt*4 + kq: m-tile mt (16 rows), k-quarter kq (chunk-local 32 k).
// bf16 hi/lo split: D = Ahi*Bhi + Ahi*Blo + Alo*Bhi  (fp32 accum).
// ---------------------------------------------------------------------------
__global__ void __launch_bounds__(REC_THREADS, 1) rnn_rec_mma(
    const float* __restrict__ pre,
    const float* __restrict__ h0,
    const float* __restrict__ wR,
    float* __restrict__ hid)
{
    extern __shared__ __align__(16) char smem[];
    uint32_t* wt  = reinterpret_cast<uint32_t*>(smem + SM_WT);   // [2][32][516]
    uint32_t* hb  = reinterpret_cast<uint32_t*>(smem + SM_HB);   // [2][2][32][68]
    float*    red = reinterpret_cast<float*>(smem + SM_RED);     // [8][16][40]

    const int tid   = threadIdx.x;
    const int wid   = tid >> 5;
    const int lane  = tid & 31;
    const int bx    = blockIdx.x;
    const int jt    = bx & 31;
    const int bs    = bx >> 5;
    const int jbase = jt * 32;
    const int bBase = bs * 32;

    // ---- Stage wR slice as bf16 hi/lo, layout [mat][n][k] (B col-major) ----
    for (int idx = tid; idx < 32 * HH; idx += REC_THREADS) {
        int n = idx & 31, k = idx >> 5;
        float v = wR[k * HH + jbase + n];
        __nv_bfloat16 hi = __float2bfloat16(v);
        __nv_bfloat16 lo = __float2bfloat16(v - __bfloat162float(hi));
        __nv_bfloat16* base = reinterpret_cast<__nv_bfloat16*>(smem + SM_WT);
        base[(size_t)n * 1032 + k]              = hi;   // mat 0 (hi)
        base[(size_t)(32 + n) * 1032 + k]       = lo;   // mat 1 (lo)
    }
    // ---- h0 -> exchange buf 0 (CTA 0 only; h0 identical across batch) ----
    if (bx == 0) {
        for (int idx = tid; idx < BB * HH; idx += REC_THREADS) {
            float v = h0[idx & (HH - 1)];
            __nv_bfloat16 hi = __float2bfloat16(v);
            __nv_bfloat16 lo = __float2bfloat16(v - __bfloat162float(hi));
            g_hx_hi[0][idx] = hi;
            g_hx_lo[0][idx] = lo;
        }
    }
    if (tid == 0) g_flags[bx][0] = 0u;   // reset for graph replays
    grid_sync();

    const int mt = wid >> 2;             // 0..1
    const int kq = wid & 3;              // 0..3
    const int lg = lane >> 2;            // 0..7 (row group)
    const int lc = lane & 3;             // 0..3 (k pair)

    // Epilogue constants: thread handles outputs o = tid*4 .. +3
    const int ebl = tid >> 3;            // 0..31 local b row
    const int ejl = (tid & 7) * 4;       // 0,4,..,28 local j
    const int eb  = bBase + ebl;

    unsigned* myFlag = &g_flags[bx][0];

    for (int t = 0; t < TT; t++) {
        // Prefetch pre for this thread's outputs.
        const float* preRow = pre + ((size_t)t * BB + eb) * HH + jbase + ejl;
        float4 pv = __ldg((const float4*)preRow);

        // Wait for the 32 producers of this b-half to publish h_(t-1).
        if (t > 0 && tid < 32) {
            const unsigned* f = &g_flags[bs * 32 + tid][0];
            unsigned cur;
            do {
                asm volatile("ld.acquire.gpu.global.u32 %0, [%1];"
                             : "=r"(cur) : "l"(f) : "memory");
            } while (cur < (unsigned)t);
        }
        __syncthreads();

        const __nv_bfloat16* hxh = g_hx_hi[t & 1] + bBase * HH;
        const __nv_bfloat16* hxl = g_hx_lo[t & 1] + bBase * HH;

        // Stage chunk c (32 rows x 128 k, hi+lo) into buf c&1 via cp.async.
        auto stage = [&](int c) {
            const int buf = c & 1;
            #pragma unroll
            for (int i = 0; i < 4; i++) {
                int L   = tid + i * REC_THREADS;   // 0..1023
                int mat = L >> 9;                  // 0 hi, 1 lo
                int rem = L & 511;
                int row = rem >> 4;                // 0..31
                int seg = rem & 15;                // 16B segments
                const __nv_bfloat16* src =
                    (mat ? hxl : hxh) + row * HH + c * CHUNK_K + seg * 8;
                uint32_t dst = (uint32_t)__cvta_generic_to_shared(
                    hb + ((buf * 2 + mat) * 32 + row) * 68 + seg * 4);
                asm volatile("cp.async.cg.shared.global [%0], [%1], 16;"
                             :: "r"(dst), "l"(src));
            }
            asm volatile("cp.async.commit_group;");
        };

        stage(0);

        float d[4][4] = {};   // [nt][4 f32]

        for (int c = 0; c < NCHUNK; c++) {
            asm volatile("cp.async.wait_group 0;");
            __syncthreads();
            if (c + 1 < NCHUNK) stage(c + 1);

            const int buf = c & 1;
            const uint32_t* hbh = hb + (buf * 2 + 0) * 32 * 68;
            const uint32_t* hbl = hb + (buf * 2 + 1) * 32 * 68;
            const uint32_t* wth = wt;
            const uint32_t* wtl = wt + 32 * 516;

            #pragma unroll
            for (int s = 0; s < 2; s++) {
                // chunk-local k word base for A; global for B
                const int aw = kq * 16 + s * 8 + lc;
                const int bw = c * 64 + kq * 16 + s * 8 + lc;
                const int ar0 = mt * 16 + lg;
                const int ar8 = ar0 + 8;

                uint32_t a0h = hbh[ar0 * 68 + aw];
                uint32_t a1h = hbh[ar8 * 68 + aw];
                uint32_t a2h = hbh[ar0 * 68 + aw + 4];
                uint32_t a3h = hbh[ar8 * 68 + aw + 4];
                uint32_t a0l = hbl[ar0 * 68 + aw];
                uint32_t a1l = hbl[ar8 * 68 + aw];
                uint32_t a2l = hbl[ar0 * 68 + aw + 4];
                uint32_t a3l = hbl[ar8 * 68 + aw + 4];

                #pragma unroll
                for (int nt = 0; nt < 4; nt++) {
                    const int nr = nt * 8 + lg;
                    uint32_t b0h = wth[nr * 516 + bw];
                    uint32_t b1h = wth[nr * 516 + bw + 4];
                    uint32_t b0l = wtl[nr * 516 + bw];
                    uint32_t b1l = wtl[nr * 516 + bw + 4];
                    mma16816(d[nt], a0h, a1h, a2h, a3h, b0h, b1h);
                    mma16816(d[nt], a0h, a1h, a2h, a3h, b0l, b1l);
                    mma16816(d[nt], a0l, a1l, a2l, a3l, b0h, b1h);
                }
            }
            __syncthreads();   // all warps done with buf before restaging it
        }

        // ---- k-reduce across warps via smem ----
        {
            float* rp = red + wid * RED_W;
            #pragma unroll
            for (int nt = 0; nt < 4; nt++) {
                int col = nt * 8 + lc * 2;
                *(float2*)&rp[lg * 40 + col]       = make_float2(d[nt][0], d[nt][1]);
                *(float2*)&rp[(lg + 8) * 40 + col] = make_float2(d[nt][2], d[nt][3]);
            }
        }
        __syncthreads();

        // ---- epilogue: sum 4 kq partials, +pre, tanh, publish ----
        float* hNew = hid + (size_t)t * (BB * HH);
        __nv_bfloat16* nxh = g_hx_hi[(t + 1) & 1];
        __nv_bfloat16* nxl = g_hx_lo[(t + 1) & 1];
        {
            const int wbase = (ebl >> 4) * 4;       // mt of this output row
            const int rrow  = (ebl & 15) * 40 + ejl;
            float4 s = make_float4(0.f, 0.f, 0.f, 0.f);
            #pragma unroll
            for (int q = 0; q < 4; q++) {
                float4 p = *(float4*)&red[(wbase + q) * RED_W + rrow];
                s.x += p.x; s.y += p.y; s.z += p.z; s.w += p.w;
            }
            float v0 = tanhf(pv.x + s.x);
            float v1 = tanhf(pv.y + s.y);
            float v2 = tanhf(pv.z + s.z);
            float v3 = tanhf(pv.w + s.w);

            *(float4*)&hNew[(size_t)eb * HH + jbase + ejl] =
                make_float4(v0, v1, v2, v3);

            __nv_bfloat16 h4[4], l4[4];
            float vv[4] = {v0, v1, v2, v3};
            #pragma unroll
            for (int i = 0; i < 4; i++) {
                h4[i] = __float2bfloat16(vv[i]);
                l4[i] = __float2bfloat16(vv[i] - __bfloat162float(h4[i]));
            }
            *(uint2*)&nxh[(size_t)eb * HH + jbase + ejl] = *(uint2*)h4;
            *(uint2*)&nxl[(size_t)eb * HH + jbase + ejl] = *(uint2*)l4;
        }

        __threadfence();
        __syncthreads();
        if (tid == 0) {
            unsigned v = (unsigned)(t + 1);
            asm volatile("st.release.gpu.global.u32 [%0], %1;"
                         :: "l"(myFlag), "r"(v) : "memory");
        }
        __syncthreads();   // red reused next step only after everyone read it
    }
}

// ---------------------------------------------------------------------------
// Launch: pre-GEMM -> persistent HMMA recurrence -> output GEMM.
// ---------------------------------------------------------------------------
extern "C" void kernel_launch(void* const* d_in, const int* in_sizes, int n_in,
                              void* d_out, int out_size)
{
    const float* x  = (const float*)d_in[0];
    const float* h0 = (const float*)d_in[1];
    const float* wI = (const float*)d_in[2];
    const float* wR = (const float*)d_in[3];
    const float* wO = (const float*)d_in[4];
    const float* bR = (const float*)d_in[5];
    const float* bO = (const float*)d_in[6];

    float* outp = (float*)d_out;            // [T,B,O]
    float* hid  = outp + OUT_ELEMS;         // [T,B,H]

    float* pre = nullptr;
    cudaGetSymbolAddress((void**)&pre, g_pre);
    cudaFuncSetAttribute(rnn_rec_mma,
                         cudaFuncAttributeMaxDynamicSharedMemorySize,
                         REC_SMEM_BYTES);

    gemm_tn_kernel<<<dim3((TT * BB) / 64, HH / 64, 1), 256>>>(
        x, wI, bR, pre, TT * BB, HH, II);

    rnn_rec_mma<<<REC_CTAS, REC_THREADS, REC_SMEM_BYTES>>>(pre, h0, wR, hid);

    gemm_tn_kernel<<<dim3((TT * BB) / 64, OO / 64, 1), 256>>>(
        hid, wO, bO, outp, TT * BB, OO, HH);
}

// round 12
// speedup vs baseline: 1.4649x; 1.4649x over previous
#include <cuda_runtime.h>
#include <cuda_bf16.h>
#include <cstdint>

// Problem constants
#define TT 512
#define BB 64
#define II 256
#define HH 1024
#define OO 256
#define OUT_ELEMS   (TT * BB * OO)

// ---------------- recurrent kernel configuration (HMMA mma.sync path) ------
#define REC_CTAS    128           // 4 b-quarters x 32 j-slices
#define REC_THREADS 256

// smem word layout (uint32 words)
// wt:  bf16 [2 mats][32 n][1032 k-pad]  -> uint32 [2][32][516]
// hb:  bf16 [2 mats][16 rows][1032 pad] -> uint32 [2][16][516]
// red: f32  [8 warps][16 rows][36 cols]
#define WT_WORDS    (2 * 32 * 516)        // 33024 words = 132096 B
#define HB_WORDS    (2 * 16 * 516)        // 16512 words =  66048 B
#define RED_WORDS   (8 * 16 * 36)         //  4608 words =  18432 B
#define SM_WT       0
#define SM_HB       WT_WORDS
#define SM_RED      (WT_WORDS + HB_WORDS)
#define REC_SMEM_BYTES ((WT_WORDS + HB_WORDS + RED_WORDS) * 4)   // 216576

// Scratch (device globals: no cudaMalloc allowed)
__device__ float g_pre[TT * BB * HH];
__device__ __align__(16) __nv_bfloat16 g_hx_hi[2][BB * HH];
__device__ __align__(16) __nv_bfloat16 g_hx_lo[2][BB * HH];
__device__ unsigned g_arrived = 0;
__device__ unsigned g_flags[REC_CTAS][32];    // one 128B line per CTA

__device__ __forceinline__ void grid_sync() {
    __syncthreads();
    if (threadIdx.x == 0) {
        __threadfence();
        unsigned ticket = atomicAdd(&g_arrived, 1u) + 1u;
        unsigned target = ((ticket + (REC_CTAS - 1u)) / REC_CTAS) * REC_CTAS;
        unsigned cur;
        do {
            asm volatile("ld.acquire.gpu.global.u32 %0, [%1];"
                         : "=r"(cur) : "l"(&g_arrived) : "memory");
        } while ((int)(cur - target) < 0);
        __threadfence();
    }
    __syncthreads();
}

__device__ __forceinline__ void mma16816(float* d, uint32_t a0, uint32_t a1,
                                         uint32_t a2, uint32_t a3,
                                         uint32_t b0, uint32_t b1) {
    asm volatile(
        "mma.sync.aligned.m16n8k16.row.col.f32.bf16.bf16.f32 "
        "{%0,%1,%2,%3}, {%4,%5,%6,%7}, {%8,%9}, {%0,%1,%2,%3};"
        : "+f"(d[0]), "+f"(d[1]), "+f"(d[2]), "+f"(d[3])
        : "r"(a0), "r"(a1), "r"(a2), "r"(a3), "r"(b0), "r"(b1));
}

// ---------------------------------------------------------------------------
// Generic fp32 GEMM:  C[M,N] = A[M,K] @ B[N,K]^T + bias[N]   (unchanged)
// ---------------------------------------------------------------------------
__global__ void __launch_bounds__(256) gemm_tn_kernel(
    const float* __restrict__ A, const float* __restrict__ B,
    const float* __restrict__ bias, float* __restrict__ C,
    int M, int N, int K)
{
    __shared__ float Ast[32][68];
    __shared__ float Bst[32][68];

    const int tid   = threadIdx.x;
    const int mBase = blockIdx.x * 64;
    const int nBase = blockIdx.y * 64;
    const int lrow  = tid >> 3;
    const int lk    = (tid & 7) << 2;
    const int tx    = tid & 15;
    const int ty    = tid >> 4;

    float acc[4][4] = {};

    const float* Ap = A + (size_t)(mBase + lrow) * K + lk;
    const float* Bp = B + (size_t)(nBase + lrow) * K + lk;

    for (int k0 = 0; k0 < K; k0 += 32) {
        float4 av0 = *(const float4*)(Ap + k0);
        float4 av1 = *(const float4*)(Ap + (size_t)32 * K + k0);
        float4 bv0 = *(const float4*)(Bp + k0);
        float4 bv1 = *(const float4*)(Bp + (size_t)32 * K + k0);
        __syncthreads();
        Ast[lk + 0][lrow] = av0.x; Ast[lk + 1][lrow] = av0.y;
        Ast[lk + 2][lrow] = av0.z; Ast[lk + 3][lrow] = av0.w;
        Ast[lk + 0][lrow + 32] = av1.x; Ast[lk + 1][lrow + 32] = av1.y;
        Ast[lk + 2][lrow + 32] = av1.z; Ast[lk + 3][lrow + 32] = av1.w;
        Bst[lk + 0][lrow] = bv0.x; Bst[lk + 1][lrow] = bv0.y;
        Bst[lk + 2][lrow] = bv0.z; Bst[lk + 3][lrow] = bv0.w;
        Bst[lk + 0][lrow + 32] = bv1.x; Bst[lk + 1][lrow + 32] = bv1.y;
        Bst[lk + 2][lrow + 32] = bv1.z; Bst[lk + 3][lrow + 32] = bv1.w;
        __syncthreads();
        #pragma unroll
        for (int k = 0; k < 32; k++) {
            float4 a = *(const float4*)&Ast[k][ty * 4];
            float4 b = *(const float4*)&Bst[k][tx * 4];
            acc[0][0] = fmaf(a.x, b.x, acc[0][0]);
            acc[0][1] = fmaf(a.x, b.y, acc[0][1]);
            acc[0][2] = fmaf(a.x, b.z, acc[0][2]);
            acc[0][3] = fmaf(a.x, b.w, acc[0][3]);
            acc[1][0] = fmaf(a.y, b.x, acc[1][0]);
            acc[1][1] = fmaf(a.y, b.y, acc[1][1]);
            acc[1][2] = fmaf(a.y, b.z, acc[1][2]);
            acc[1][3] = fmaf(a.y, b.w, acc[1][3]);
            acc[2][0] = fmaf(a.z, b.x, acc[2][0]);
            acc[2][1] = fmaf(a.z, b.y, acc[2][1]);
            acc[2][2] = fmaf(a.z, b.z, acc[2][2]);
            acc[2][3] = fmaf(a.z, b.w, acc[2][3]);
            acc[3][0] = fmaf(a.w, b.x, acc[3][0]);
            acc[3][1] = fmaf(a.w, b.y, acc[3][1]);
            acc[3][2] = fmaf(a.w, b.z, acc[3][2]);
            acc[3][3] = fmaf(a.w, b.w, acc[3][3]);
        }
    }

    const float b0 = bias[nBase + tx * 4 + 0];
    const float b1 = bias[nBase + tx * 4 + 1];
    const float b2 = bias[nBase + tx * 4 + 2];
    const float b3 = bias[nBase + tx * 4 + 3];
    #pragma unroll
    for (int i = 0; i < 4; i++) {
        float4 o;
        o.x = acc[i][0] + b0; o.y = acc[i][1] + b1;
        o.z = acc[i][2] + b2; o.w = acc[i][3] + b3;
        *(float4*)&C[(size_t)(mBase + ty * 4 + i) * N + nBase + tx * 4] = o;
    }
}

// ---------------------------------------------------------------------------
// HMMA persistent recurrence: h_t = tanh(pre_t + h_{t-1} @ wR), 512 steps.
// 128 CTAs: bq = bx>>5 (16 b-rows), jt = bx&31 (32 j-cols).
// 8 warps = 8-way k-split; warp kq covers k in [kq*64, +64) of each k-half.
// bf16 hi/lo split: D = Ahi*Bhi + Ahi*Blo + Alo*Bhi (fp32 accum).
// h staged once/step into smem via 2 cp.async groups (k-halves, pipelined).
// ---------------------------------------------------------------------------
__global__ void __launch_bounds__(REC_THREADS, 1) rnn_rec_mma(
    const float* __restrict__ pre,
    const float* __restrict__ h0,
    const float* __restrict__ wR,
    float* __restrict__ hid)
{
    extern __shared__ __align__(16) uint32_t smw[];
    uint32_t* wt  = smw + SM_WT;                  // [2][32][516]
    uint32_t* hb  = smw + SM_HB;                  // [2][16][516]
    float*    red = reinterpret_cast<float*>(smw + SM_RED);  // [8][16][36]

    const int tid   = threadIdx.x;
    const int wid   = tid >> 5;
    const int lane  = tid & 31;
    const int bx    = blockIdx.x;
    const int jt    = bx & 31;
    const int bq    = bx >> 5;
    const int jbase = jt * 32;
    const int bBase = bq * 16;

    // ---- Stage wR slice as bf16 hi/lo, layout [mat][n][k] ----
    {
        __nv_bfloat16* wb = reinterpret_cast<__nv_bfloat16*>(wt);
        for (int idx = tid; idx < 32 * HH; idx += REC_THREADS) {
            int n = idx & 31, k = idx >> 5;
            float v = wR[k * HH + jbase + n];
            __nv_bfloat16 hi = __float2bfloat16(v);
            __nv_bfloat16 lo = __float2bfloat16(v - __bfloat162float(hi));
            wb[(size_t)n * 1032 + k]        = hi;   // mat 0
            wb[(size_t)(32 + n) * 1032 + k] = lo;   // mat 1
        }
    }
    // ---- h0 -> exchange buf 0 (CTA 0 only) ----
    if (bx == 0) {
        for (int idx = tid; idx < BB * HH; idx += REC_THREADS) {
            float v = h0[idx & (HH - 1)];
            __nv_bfloat16 hi = __float2bfloat16(v);
            __nv_bfloat16 lo = __float2bfloat16(v - __bfloat162float(hi));
            g_hx_hi[0][idx] = hi;
            g_hx_lo[0][idx] = lo;
        }
    }
    if (tid == 0) g_flags[bx][0] = 0u;   // reset for graph replays
    grid_sync();

    const int kq = wid;                  // 0..7 k-split
    const int lg = lane >> 2;            // 0..7
    const int lc = lane & 3;             // 0..3

    // Epilogue constants: thread handles 2 outputs (row ebl, cols ejl, ejl+1)
    const int ebl = tid >> 4;            // 0..15
    const int ejl = (tid & 15) * 2;      // 0,2,..,30
    const int eb  = bBase + ebl;

    unsigned* myFlag = &g_flags[bx][0];
    const uint32_t hb_sm = (uint32_t)__cvta_generic_to_shared(hb);

    for (int t = 0; t < TT; t++) {
        // Prefetch pre for this thread's outputs.
        const float* preRow = pre + ((size_t)t * BB + eb) * HH + jbase + ejl;
        float2 pv = __ldg((const float2*)preRow);

        // Wait for the 32 producers of this b-quarter to publish h_(t-1).
        if (t > 0 && tid < 32) {
            const unsigned* f = &g_flags[bq * 32 + tid][0];
            unsigned cur;
            do {
                asm volatile("ld.acquire.gpu.global.u32 %0, [%1];"
                             : "=r"(cur) : "l"(f) : "memory");
            } while (cur < (unsigned)t);
        }
        __syncthreads();   // everyone past epilogue of t-1; hb/red reusable

        const __nv_bfloat16* hxh = g_hx_hi[t & 1] + bBase * HH;
        const __nv_bfloat16* hxl = g_hx_lo[t & 1] + bBase * HH;

        // Stage k-half g: 16 rows x 512 k x {hi,lo} = 32 KB, one commit group.
        auto stage_half = [&](int g) {
            #pragma unroll
            for (int i = 0; i < 8; i++) {
                int L   = tid + i * REC_THREADS;   // 0..2047
                int mat = L >> 10;                 // 0 hi, 1 lo
                int rem = L & 1023;
                int row = rem >> 6;                // 0..15
                int seg = rem & 63;                // 16B segment in half
                const __nv_bfloat16* src =
                    (mat ? hxl : hxh) + row * HH + g * 512 + seg * 8;
                uint32_t dst = hb_sm +
                    (((mat * 16 + row) * 516 + g * 256 + seg * 4) << 2);
                asm volatile("cp.async.cg.shared.global [%0], [%1], 16;"
                             :: "r"(dst), "l"(src));
            }
            asm volatile("cp.async.commit_group;");
        };

        stage_half(0);
        stage_half(1);

        float d[4][4] = {};   // [nt][4 f32]

        const uint32_t* hbh = hb;
        const uint32_t* hbl = hb + 16 * 516;
        const uint32_t* wth = wt;
        const uint32_t* wtl = wt + 32 * 516;

        #pragma unroll
        for (int g = 0; g < 2; g++) {
            if (g == 0) asm volatile("cp.async.wait_group 1;");
            else        asm volatile("cp.async.wait_group 0;");
            __syncthreads();

            #pragma unroll
            for (int s = 0; s < 4; s++) {
                // warp kq's k-words in half g
                const int w = g * 256 + kq * 32 + s * 8 + lc;

                uint32_t a0h = hbh[lg * 516 + w];
                uint32_t a1h = hbh[(lg + 8) * 516 + w];
                uint32_t a2h = hbh[lg * 516 + w + 4];
                uint32_t a3h = hbh[(lg + 8) * 516 + w + 4];
                uint32_t a0l = hbl[lg * 516 + w];
                uint32_t a1l = hbl[(lg + 8) * 516 + w];
                uint32_t a2l = hbl[lg * 516 + w + 4];
                uint32_t a3l = hbl[(lg + 8) * 516 + w + 4];

                #pragma unroll
                for (int nt = 0; nt < 4; nt++) {
                    const int nr = nt * 8 + lg;
                    uint32_t b0h = wth[nr * 516 + w];
                    uint32_t b1h = wth[nr * 516 + w + 4];
                    uint32_t b0l = wtl[nr * 516 + w];
                    uint32_t b1l = wtl[nr * 516 + w + 4];
                    mma16816(d[nt], a0h, a1h, a2h, a3h, b0h, b1h);
                    mma16816(d[nt], a0h, a1h, a2h, a3h, b0l, b1l);
                    mma16816(d[nt], a0l, a1l, a2l, a3l, b0h, b1h);
                }
            }
        }

        // ---- write k-split partials to red ----
        {
            float* rp = red + wid * 576;           // 16*36
            #pragma unroll
            for (int nt = 0; nt < 4; nt++) {
                int col = nt * 8 + lc * 2;
                *(float2*)&rp[lg * 36 + col]       = make_float2(d[nt][0], d[nt][1]);
                *(float2*)&rp[(lg + 8) * 36 + col] = make_float2(d[nt][2], d[nt][3]);
            }
        }
        __syncthreads();

        // ---- epilogue: reduce 8 partials, +pre, tanh, publish ----
        float* hNew = hid + (size_t)t * (BB * HH);
        __nv_bfloat16* nxh = g_hx_hi[(t + 1) & 1];
        __nv_bfloat16* nxl = g_hx_lo[(t + 1) & 1];
        {
            float s0 = 0.f, s1 = 0.f;
            #pragma unroll
            for (int q = 0; q < 8; q++) {
                float2 p = *(float2*)&red[q * 576 + ebl * 36 + ejl];
                s0 += p.x; s1 += p.y;
            }
            float v0 = tanhf(pv.x + s0);
            float v1 = tanhf(pv.y + s1);

            *(float2*)&hNew[(size_t)eb * HH + jbase + ejl] = make_float2(v0, v1);

            __nv_bfloat16 h2[2], l2[2];
            h2[0] = __float2bfloat16(v0);
            h2[1] = __float2bfloat16(v1);
            l2[0] = __float2bfloat16(v0 - __bfloat162float(h2[0]));
            l2[1] = __float2bfloat16(v1 - __bfloat162float(h2[1]));
            *(uint32_t*)&nxh[(size_t)eb * HH + jbase + ejl] = *(uint32_t*)h2;
            *(uint32_t*)&nxl[(size_t)eb * HH + jbase + ejl] = *(uint32_t*)l2;
        }

        __threadfence();
        __syncthreads();
        if (tid == 0) {
            unsigned v = (unsigned)(t + 1);
            asm volatile("st.release.gpu.global.u32 [%0], %1;"
                         :: "l"(myFlag), "r"(v) : "memory");
        }
    }
}

// ---------------------------------------------------------------------------
// Launch: pre-GEMM -> persistent HMMA recurrence -> output GEMM.
// ---------------------------------------------------------------------------
extern "C" void kernel_launch(void* const* d_in, const int* in_sizes, int n_in,
                              void* d_out, int out_size)
{
    const float* x  = (const float*)d_in[0];
    const float* h0 = (const float*)d_in[1];
    const float* wI = (const float*)d_in[2];
    const float* wR = (const float*)d_in[3];
    const float* wO = (const float*)d_in[4];
    const float* bR = (const float*)d_in[5];
    const float* bO = (const float*)d_in[6];

    float* outp = (float*)d_out;            // [T,B,O]
    float* hid  = outp + OUT_ELEMS;         // [T,B,H]

    float* pre = nullptr;
    cudaGetSymbolAddress((void**)&pre, g_pre);
    cudaFuncSetAttribute(rnn_rec_mma,
                         cudaFuncAttributeMaxDynamicSharedMemorySize,
                         REC_SMEM_BYTES);

    gemm_tn_kernel<<<dim3((TT * BB) / 64, HH / 64, 1), 256>>>(
        x, wI, bR, pre, TT * BB, HH, II);

    rnn_rec_mma<<<REC_CTAS, REC_THREADS, REC_SMEM_BYTES>>>(pre, h0, wR, hid);

    gemm_tn_kernel<<<dim3((TT * BB) / 64, OO / 64, 1), 256>>>(
        hid, wO, bO, outp, TT * BB, OO, HH);
}

// round 14
// speedup vs baseline: 1.8609x; 1.2703x over previous
#include <cuda_runtime.h>
#include <cuda_bf16.h>
#include <cstdint>

// Problem constants
#define TT 512
#define BB 64
#define II 256
#define HH 1024
#define OO 256
#define OUT_ELEMS   (TT * BB * OO)

// ---------------- recurrent kernel configuration (HMMA mma.sync path) ------
#define REC_CTAS    128           // 4 b-quarters x 32 j-slices
#define REC_THREADS 256

// smem word layout (uint32 words)
#define WT_WORDS    (2 * 32 * 516)        // 33024 words = 132096 B
#define HB_WORDS    (2 * 16 * 516)        // 16512 words =  66048 B
#define RED_WORDS   (8 * 16 * 36)         //  4608 words =  18432 B
#define SM_WT       0
#define SM_HB       WT_WORDS
#define SM_RED      (WT_WORDS + HB_WORDS)
#define REC_SMEM_BYTES ((WT_WORDS + HB_WORDS + RED_WORDS) * 4)   // 216576

// ---------------- split-bf16 HMMA GEMM configuration -----------------------
#define GEMM_SMEM_WORDS (2 * 9216)        // sA 9216 + sB 9216 words
#define GEMM_SMEM_BYTES (GEMM_SMEM_WORDS * 4)   // 73728

// Scratch (device globals: no cudaMalloc allowed)
__device__ float g_pre[TT * BB * HH];
__device__ __align__(16) __nv_bfloat16 g_xh[TT * BB * II];
__device__ __align__(16) __nv_bfloat16 g_xl[TT * BB * II];
__device__ __align__(16) __nv_bfloat16 g_wih[HH * II];
__device__ __align__(16) __nv_bfloat16 g_wil[HH * II];
__device__ __align__(16) __nv_bfloat16 g_woh[OO * HH];
__device__ __align__(16) __nv_bfloat16 g_wol[OO * HH];
__device__ __align__(16) __nv_bfloat16 g_hhh[(TT + 1) * BB * HH];  // h history hi
__device__ __align__(16) __nv_bfloat16 g_hhl[(TT + 1) * BB * HH];  // h history lo
__device__ unsigned g_arrived = 0;
__device__ unsigned g_flags[REC_CTAS][32];    // one 128B line per CTA

__device__ __forceinline__ void grid_sync() {
    __syncthreads();
    if (threadIdx.x == 0) {
        __threadfence();
        unsigned ticket = atomicAdd(&g_arrived, 1u) + 1u;
        unsigned target = ((ticket + (REC_CTAS - 1u)) / REC_CTAS) * REC_CTAS;
        unsigned cur;
        do {
            asm volatile("ld.acquire.gpu.global.u32 %0, [%1];"
                         : "=r"(cur) : "l"(&g_arrived) : "memory");
        } while ((int)(cur - target) < 0);
        __threadfence();
    }
    __syncthreads();
}

__device__ __forceinline__ void mma16816(float* d, uint32_t a0, uint32_t a1,
                                         uint32_t a2, uint32_t a3,
                                         uint32_t b0, uint32_t b1) {
    asm volatile(
        "mma.sync.aligned.m16n8k16.row.col.f32.bf16.bf16.f32 "
        "{%0,%1,%2,%3}, {%4,%5,%6,%7}, {%8,%9}, {%0,%1,%2,%3};"
        : "+f"(d[0]), "+f"(d[1]), "+f"(d[2]), "+f"(d[3])
        : "r"(a0), "r"(a1), "r"(a2), "r"(a3), "r"(b0), "r"(b1));
}

// ---------------------------------------------------------------------------
// fp32 -> bf16 hi/lo split (vectorized by 4)
// ---------------------------------------------------------------------------
__global__ void __launch_bounds__(256) split_kernel(
    const float* __restrict__ src, __nv_bfloat16* __restrict__ hi,
    __nv_bfloat16* __restrict__ lo, int n4)
{
    int i = blockIdx.x * 256 + threadIdx.x;
    if (i >= n4) return;
    float4 v = ((const float4*)src)[i];
    __nv_bfloat16 h[4], l[4];
    float vv[4] = {v.x, v.y, v.z, v.w};
    #pragma unroll
    for (int j = 0; j < 4; j++) {
        h[j] = __float2bfloat16(vv[j]);
        l[j] = __float2bfloat16(vv[j] - __bfloat162float(h[j]));
    }
    ((uint2*)hi)[i] = *(uint2*)h;
    ((uint2*)lo)[i] = *(uint2*)l;
}

// ---------------------------------------------------------------------------
// Split-bf16 HMMA GEMM: C[M,N] = (Ah+Al)[M,K] @ (Bh+Bl)[N,K]^T + bias[N]
// (exactly: Ah*Bh + Ah*Bl + Al*Bh; fp32 accumulate)
// CTA tile 64x64, BK=64 double-buffered cp.async; 8 warps = 2m x 4n;
// warp tile 32m x 16n = 2x2 m16n8k16 tiles. Fragment indexing identical to
// the verified recurrent kernel (smem row stride 36 words; 36%32==4).
// ---------------------------------------------------------------------------
__global__ void __launch_bounds__(256) gemm_mma_split(
    const __nv_bfloat16* __restrict__ Ah, const __nv_bfloat16* __restrict__ Al,
    const __nv_bfloat16* __restrict__ Bh, const __nv_bfloat16* __restrict__ Bl,
    const float* __restrict__ bias, float* __restrict__ C,
    int M, int N, int K)
{
    extern __shared__ __align__(16) uint32_t sm[];
    uint32_t* sA = sm;                 // [2 buf][2 mat][64 row][36 w]
    uint32_t* sB = sm + 9216;          // same

    const int tid   = threadIdx.x;
    const int wid   = tid >> 5;
    const int lane  = tid & 31;
    const int mBase = blockIdx.x * 64;
    const int nBase = blockIdx.y * 64;
    const int wm    = wid >> 2;        // 0..1
    const int wn    = wid & 3;         // 0..3
    const int lg    = lane >> 2;       // 0..7
    const int lc    = lane & 3;        // 0..3

    const uint32_t sA_sm = (uint32_t)__cvta_generic_to_shared(sA);
    const uint32_t sB_sm = (uint32_t)__cvta_generic_to_shared(sB);

    // stage chunk c into buffer buf (A and B, hi+lo): 8 x 16B per thread
    auto stage = [&](int c, int buf) {
        #pragma unroll
        for (int i = 0; i < 4; i++) {
            int L   = tid + i * 256;       // 0..1023
            int mat = L >> 9;
            int rem = L & 511;
            int row = rem >> 3;            // 0..63
            int seg = rem & 7;             // 16B segment
            const __nv_bfloat16* srcA =
                (mat ? Al : Ah) + (size_t)(mBase + row) * K + c * 64 + seg * 8;
            uint32_t dstA = sA_sm +
                (((buf * 2 + mat) * 64 + row) * 36 + seg * 4) * 4;
            asm volatile("cp.async.cg.shared.global [%0], [%1], 16;"
                         :: "r"(dstA), "l"(srcA));
            const __nv_bfloat16* srcB =
                (mat ? Bl : Bh) + (size_t)(nBase + row) * K + c * 64 + seg * 8;
            uint32_t dstB = sB_sm +
                (((buf * 2 + mat) * 64 + row) * 36 + seg * 4) * 4;
            asm volatile("cp.async.cg.shared.global [%0], [%1], 16;"
                         :: "r"(dstB), "l"(srcB));
        }
        asm volatile("cp.async.commit_group;");
    };

    float acc[2][2][4] = {};
    const int NC = K >> 6;

    stage(0, 0);

    for (int c = 0; c < NC; c++) {
        const int buf = c & 1;
        if (c + 1 < NC) {
            stage(c + 1, buf ^ 1);
            asm volatile("cp.async.wait_group 1;");
        } else {
            asm volatile("cp.async.wait_group 0;");
        }
        __syncthreads();

        const uint32_t* aH = sA + (buf * 2 + 0) * 2304;   // 64*36
        const uint32_t* aL = sA + (buf * 2 + 1) * 2304;
        const uint32_t* bH = sB + (buf * 2 + 0) * 2304;
        const uint32_t* bL = sB + (buf * 2 + 1) * 2304;

        #pragma unroll
        for (int s = 0; s < 4; s++) {
            const int w = s * 8 + lc;
            uint32_t ah[2][4], al[2][4], bh[2][2], bl[2][2];
            #pragma unroll
            for (int mt = 0; mt < 2; mt++) {
                const int r = wm * 32 + mt * 16 + lg;
                ah[mt][0] = aH[r * 36 + w];
                ah[mt][1] = aH[(r + 8) * 36 + w];
                ah[mt][2] = aH[r * 36 + w + 4];
                ah[mt][3] = aH[(r + 8) * 36 + w + 4];
                al[mt][0] = aL[r * 36 + w];
                al[mt][1] = aL[(r + 8) * 36 + w];
                al[mt][2] = aL[r * 36 + w + 4];
                al[mt][3] = aL[(r + 8) * 36 + w + 4];
            }
            #pragma unroll
            for (int nt = 0; nt < 2; nt++) {
                const int r = wn * 16 + nt * 8 + lg;
                bh[nt][0] = bH[r * 36 + w];
                bh[nt][1] = bH[r * 36 + w + 4];
                bl[nt][0] = bL[r * 36 + w];
                bl[nt][1] = bL[r * 36 + w + 4];
            }
            #pragma unroll
            for (int mt = 0; mt < 2; mt++)
                #pragma unroll
                for (int nt = 0; nt < 2; nt++) {
                    mma16816(acc[mt][nt], ah[mt][0], ah[mt][1], ah[mt][2],
                             ah[mt][3], bh[nt][0], bh[nt][1]);
                    mma16816(acc[mt][nt], ah[mt][0], ah[mt][1], ah[mt][2],
                             ah[mt][3], bl[nt][0], bl[nt][1]);
                    mma16816(acc[mt][nt], al[mt][0], al[mt][1], al[mt][2],
                             al[mt][3], bh[nt][0], bh[nt][1]);
                }
        }
        __syncthreads();
    }

    // Epilogue: accumulators -> C (+bias). Lane l: rows lg, lg+8; cols lc*2..+1
    #pragma unroll
    for (int mt = 0; mt < 2; mt++) {
        #pragma unroll
        for (int nt = 0; nt < 2; nt++) {
            const int row = mBase + wm * 32 + mt * 16 + lg;
            const int col = nBase + wn * 16 + nt * 8 + lc * 2;
            const float b0 = __ldg(bias + col);
            const float b1 = __ldg(bias + col + 1);
            float* d = acc[mt][nt];
            *(float2*)&C[(size_t)row * N + col] =
                make_float2(d[0] + b0, d[1] + b1);
            *(float2*)&C[(size_t)(row + 8) * N + col] =
                make_float2(d[2] + b0, d[3] + b1);
        }
    }
}

// ---------------------------------------------------------------------------
// HMMA persistent recurrence (unchanged from R12 except: h exchange is now a
// full-history array g_hhh/g_hhl[(T+1)][B*H]; slot 0 = h0, slot t+1 = h_t).
// ---------------------------------------------------------------------------
__global__ void __launch_bounds__(REC_THREADS, 1) rnn_rec_mma(
    const float* __restrict__ pre,
    const float* __restrict__ h0,
    const float* __restrict__ wR,
    float* __restrict__ hid)
{
    extern __shared__ __align__(16) uint32_t smw[];
    uint32_t* wt  = smw + SM_WT;                  // [2][32][516]
    uint32_t* hb  = smw + SM_HB;                  // [2][16][516]
    float*    red = reinterpret_cast<float*>(smw + SM_RED);  // [8][16][36]

    const int tid   = threadIdx.x;
    const int wid   = tid >> 5;
    const int lane  = tid & 31;
    const int bx    = blockIdx.x;
    const int jt    = bx & 31;
    const int bq    = bx >> 5;
    const int jbase = jt * 32;
    const int bBase = bq * 16;

    // ---- Stage wR slice as bf16 hi/lo, layout [mat][n][k] ----
    {
        __nv_bfloat16* wb = reinterpret_cast<__nv_bfloat16*>(wt);
        for (int idx = tid; idx < 32 * HH; idx += REC_THREADS) {
            int n = idx & 31, k = idx >> 5;
            float v = wR[k * HH + jbase + n];
            __nv_bfloat16 hi = __float2bfloat16(v);
            __nv_bfloat16 lo = __float2bfloat16(v - __bfloat162float(hi));
            wb[(size_t)n * 1032 + k]        = hi;   // mat 0
            wb[(size_t)(32 + n) * 1032 + k] = lo;   // mat 1
        }
    }
    // ---- h0 -> history slot 0 (CTA 0 only) ----
    if (bx == 0) {
        for (int idx = tid; idx < BB * HH; idx += REC_THREADS) {
            float v = h0[idx & (HH - 1)];
            __nv_bfloat16 hi = __float2bfloat16(v);
            __nv_bfloat16 lo = __float2bfloat16(v - __bfloat162float(hi));
            g_hhh[idx] = hi;
            g_hhl[idx] = lo;
        }
    }
    if (tid == 0) g_flags[bx][0] = 0u;   // reset for graph replays
    grid_sync();

    const int kq = wid;                  // 0..7 k-split
    const int lg = lane >> 2;            // 0..7
    const int lc = lane & 3;             // 0..3

    const int ebl = tid >> 4;            // 0..15
    const int ejl = (tid & 15) * 2;      // 0,2,..,30
    const int eb  = bBase + ebl;

    unsigned* myFlag = &g_flags[bx][0];
    const uint32_t hb_sm = (uint32_t)__cvta_generic_to_shared(hb);

    for (int t = 0; t < TT; t++) {
        const float* preRow = pre + ((size_t)t * BB + eb) * HH + jbase + ejl;
        float2 pv = __ldg((const float2*)preRow);

        if (t > 0 && tid < 32) {
            const unsigned* f = &g_flags[bq * 32 + tid][0];
            unsigned cur;
            do {
                asm volatile("ld.acquire.gpu.global.u32 %0, [%1];"
                             : "=r"(cur) : "l"(f) : "memory");
            } while (cur < (unsigned)t);
        }
        __syncthreads();

        const __nv_bfloat16* hxh = g_hhh + (size_t)t * (BB * HH) + bBase * HH;
        const __nv_bfloat16* hxl = g_hhl + (size_t)t * (BB * HH) + bBase * HH;

        auto stage_half = [&](int g) {
            #pragma unroll
            for (int i = 0; i < 8; i++) {
                int L   = tid + i * REC_THREADS;   // 0..2047
                int mat = L >> 10;                 // 0 hi, 1 lo
                int rem = L & 1023;
                int row = rem >> 6;                // 0..15
                int seg = rem & 63;                // 16B segment in half
                const __nv_bfloat16* src =
                    (mat ? hxl : hxh) + row * HH + g * 512 + seg * 8;
                uint32_t dst = hb_sm +
                    (((mat * 16 + row) * 516 + g * 256 + seg * 4) << 2);
                asm volatile("cp.async.cg.shared.global [%0], [%1], 16;"
                             :: "r"(dst), "l"(src));
            }
            asm volatile("cp.async.commit_group;");
        };

        stage_half(0);
        stage_half(1);

        float d[4][4] = {};

        const uint32_t* hbh = hb;
        const uint32_t* hbl = hb + 16 * 516;
        const uint32_t* wth = wt;
        const uint32_t* wtl = wt + 32 * 516;

        #pragma unroll
        for (int g = 0; g < 2; g++) {
            if (g == 0) asm volatile("cp.async.wait_group 1;");
            else        asm volatile("cp.async.wait_group 0;");
            __syncthreads();

            #pragma unroll
            for (int s = 0; s < 4; s++) {
                const int w = g * 256 + kq * 32 + s * 8 + lc;

                uint32_t a0h = hbh[lg * 516 + w];
                uint32_t a1h = hbh[(lg + 8) * 516 + w];
                uint32_t a2h = hbh[lg * 516 + w + 4];
                uint32_t a3h = hbh[(lg + 8) * 516 + w + 4];
                uint32_t a0l = hbl[lg * 516 + w];
                uint32_t a1l = hbl[(lg + 8) * 516 + w];
                uint32_t a2l = hbl[lg * 516 + w + 4];
                uint32_t a3l = hbl[(lg + 8) * 516 + w + 4];

                #pragma unroll
                for (int nt = 0; nt < 4; nt++) {
                    const int nr = nt * 8 + lg;
                    uint32_t b0h = wth[nr * 516 + w];
                    uint32_t b1h = wth[nr * 516 + w + 4];
                    uint32_t b0l = wtl[nr * 516 + w];
                    uint32_t b1l = wtl[nr * 516 + w + 4];
                    mma16816(d[nt], a0h, a1h, a2h, a3h, b0h, b1h);
                    mma16816(d[nt], a0h, a1h, a2h, a3h, b0l, b1l);
                    mma16816(d[nt], a0l, a1l, a2l, a3l, b0h, b1h);
                }
            }
        }

        // ---- write k-split partials to red ----
        {
            float* rp = red + wid * 576;
            #pragma unroll
            for (int nt = 0; nt < 4; nt++) {
                int col = nt * 8 + lc * 2;
                *(float2*)&rp[lg * 36 + col]       = make_float2(d[nt][0], d[nt][1]);
                *(float2*)&rp[(lg + 8) * 36 + col] = make_float2(d[nt][2], d[nt][3]);
            }
        }
        __syncthreads();

        // ---- epilogue: reduce 8 partials, +pre, tanh, publish ----
        float* hNew = hid + (size_t)t * (BB * HH);
        __nv_bfloat16* nxh = g_hhh + (size_t)(t + 1) * (BB * HH);
        __nv_bfloat16* nxl = g_hhl + (size_t)(t + 1) * (BB * HH);
        {
            float s0 = 0.f, s1 = 0.f;
            #pragma unroll
            for (int q = 0; q < 8; q++) {
                float2 p = *(float2*)&red[q * 576 + ebl * 36 + ejl];
                s0 += p.x; s1 += p.y;
            }
            float v0 = tanhf(pv.x + s0);
            float v1 = tanhf(pv.y + s1);

            *(float2*)&hNew[(size_t)eb * HH + jbase + ejl] = make_float2(v0, v1);

            __nv_bfloat16 h2[2], l2[2];
            h2[0] = __float2bfloat16(v0);
            h2[1] = __float2bfloat16(v1);
            l2[0] = __float2bfloat16(v0 - __bfloat162float(h2[0]));
            l2[1] = __float2bfloat16(v1 - __bfloat162float(h2[1]));
            *(uint32_t*)&nxh[(size_t)eb * HH + jbase + ejl] = *(uint32_t*)h2;
            *(uint32_t*)&nxl[(size_t)eb * HH + jbase + ejl] = *(uint32_t*)l2;
        }

        __threadfence();
        __syncthreads();
        if (tid == 0) {
            unsigned v = (unsigned)(t + 1);
            asm volatile("st.release.gpu.global.u32 [%0], %1;"
                         :: "l"(myFlag), "r"(v) : "memory");
        }
    }
}

// ---------------------------------------------------------------------------
// Launch: splits -> HMMA pre-GEMM -> persistent HMMA recurrence -> HMMA
// out-GEMM (out-GEMM reads the recurrent kernel's bf16 h history directly).
// ---------------------------------------------------------------------------
extern "C" void kernel_launch(void* const* d_in, const int* in_sizes, int n_in,
                              void* d_out, int out_size)
{
    const float* x  = (const float*)d_in[0];
    const float* h0 = (const float*)d_in[1];
    const float* wI = (const float*)d_in[2];
    const float* wR = (const float*)d_in[3];
    const float* wO = (const float*)d_in[4];
    const float* bR = (const float*)d_in[5];
    const float* bO = (const float*)d_in[6];

    float* outp = (float*)d_out;            // [T,B,O]
    float* hid  = outp + OUT_ELEMS;         // [T,B,H]

    float* pre = nullptr;
    cudaGetSymbolAddress((void**)&pre, g_pre);
    __nv_bfloat16 *xh, *xl, *wih, *wil, *woh, *wol, *hhh, *hhl;
    cudaGetSymbolAddress((void**)&xh,  g_xh);
    cudaGetSymbolAddress((void**)&xl,  g_xl);
    cudaGetSymbolAddress((void**)&wih, g_wih);
    cudaGetSymbolAddress((void**)&wil, g_wil);
    cudaGetSymbolAddress((void**)&woh, g_woh);
    cudaGetSymbolAddress((void**)&wol, g_wol);
    cudaGetSymbolAddress((void**)&hhh, g_hhh);
    cudaGetSymbolAddress((void**)&hhl, g_hhl);

    cudaFuncSetAttribute(rnn_rec_mma,
                         cudaFuncAttributeMaxDynamicSharedMemorySize,
                         REC_SMEM_BYTES);
    cudaFuncSetAttribute(gemm_mma_split,
                         cudaFuncAttributeMaxDynamicSharedMemorySize,
                         GEMM_SMEM_BYTES);

    // fp32 -> bf16 hi/lo splits
    split_kernel<<<(TT * BB * II / 4 + 255) / 256, 256>>>(x, xh, xl, TT * BB * II / 4);
    split_kernel<<<(HH * II / 4 + 255) / 256, 256>>>(wI, wih, wil, HH * II / 4);
    split_kernel<<<(OO * HH / 4 + 255) / 256, 256>>>(wO, woh, wol, OO * HH / 4);

    // pre[T*B, H] = x @ wI^T + bR   (HMMA split)
    gemm_mma_split<<<dim3(TT * BB / 64, HH / 64), 256, GEMM_SMEM_BYTES>>>(
        xh, xl, wih, wil, bR, pre, TT * BB, HH, II);

    // recurrence (writes hid fp32 + bf16 hi/lo history)
    rnn_rec_mma<<<REC_CTAS, REC_THREADS, REC_SMEM_BYTES>>>(pre, h0, wR, hid);

    // outputs[T*B, O] = hid @ wO^T + bO  (HMMA split, A = bf16 history slot 1+)
    gemm_mma_split<<<dim3(TT * BB / 64, OO / 64), 256, GEMM_SMEM_BYTES>>>(
        hhh + BB * HH, hhl + BB * HH, woh, wol, bO, outp, TT * BB, OO, HH);
}

// round 15
// speedup vs baseline: 1.9242x; 1.0341x over previous
#include <cuda_runtime.h>
#include <cuda_bf16.h>
#include <cstdint>

// Problem constants
#define TT 512
#define BB 64
#define II 256
#define HH 1024
#define OO 256
#define OUT_ELEMS   (TT * BB * OO)

// ---------------- recurrent kernel configuration (HMMA mma.sync path) ------
#define REC_CTAS    128           // 4 b-quarters x 32 j-slices
#define REC_THREADS 256

// smem word layout (uint32 words)
#define WT_WORDS    (2 * 32 * 516)        // 33024 words = 132096 B
#define HB_WORDS    (2 * 16 * 516)        // 16512 words =  66048 B
#define RED_WORDS   (8 * 16 * 36)         //  4608 words =  18432 B
#define SM_WT       0
#define SM_HB       WT_WORDS
#define SM_RED      (WT_WORDS + HB_WORDS)
#define REC_SMEM_BYTES ((WT_WORDS + HB_WORDS + RED_WORDS) * 4)   // 216576

// ---------------- split-bf16 HMMA GEMM configuration -----------------------
#define GEMM_SMEM_WORDS (2 * 9216)        // sA 9216 + sB 9216 words
#define GEMM_SMEM_BYTES (GEMM_SMEM_WORDS * 4)   // 73728

// Scratch (device globals: no cudaMalloc allowed)
__device__ float g_pre[TT * BB * HH];
__device__ __align__(16) __nv_bfloat16 g_xh[TT * BB * II];
__device__ __align__(16) __nv_bfloat16 g_xl[TT * BB * II];
__device__ __align__(16) __nv_bfloat16 g_wih[HH * II];
__device__ __align__(16) __nv_bfloat16 g_wil[HH * II];
__device__ __align__(16) __nv_bfloat16 g_woh[OO * HH];
__device__ __align__(16) __nv_bfloat16 g_wol[OO * HH];
__device__ __align__(16) __nv_bfloat16 g_hhh[(TT + 1) * BB * HH];  // h history hi
__device__ __align__(16) __nv_bfloat16 g_hhl[(TT + 1) * BB * HH];  // h history lo
__device__ unsigned g_arrived = 0;
__device__ unsigned g_flags[REC_CTAS][32];    // one 128B line per CTA

__device__ __forceinline__ void grid_sync() {
    __syncthreads();
    if (threadIdx.x == 0) {
        __threadfence();
        unsigned ticket = atomicAdd(&g_arrived, 1u) + 1u;
        unsigned target = ((ticket + (REC_CTAS - 1u)) / REC_CTAS) * REC_CTAS;
        unsigned cur;
        do {
            asm volatile("ld.acquire.gpu.global.u32 %0, [%1];"
                         : "=r"(cur) : "l"(&g_arrived) : "memory");
        } while ((int)(cur - target) < 0);
        __threadfence();
    }
    __syncthreads();
}

__device__ __forceinline__ void mma16816(float* d, uint32_t a0, uint32_t a1,
                                         uint32_t a2, uint32_t a3,
                                         uint32_t b0, uint32_t b1) {
    asm volatile(
        "mma.sync.aligned.m16n8k16.row.col.f32.bf16.bf16.f32 "
        "{%0,%1,%2,%3}, {%4,%5,%6,%7}, {%8,%9}, {%0,%1,%2,%3};"
        : "+f"(d[0]), "+f"(d[1]), "+f"(d[2]), "+f"(d[3])
        : "r"(a0), "r"(a1), "r"(a2), "r"(a3), "r"(b0), "r"(b1));
}

// ---------------------------------------------------------------------------
// fp32 -> bf16 hi/lo split (vectorized by 4)
// ---------------------------------------------------------------------------
__global__ void __launch_bounds__(256) split_kernel(
    const float* __restrict__ src, __nv_bfloat16* __restrict__ hi,
    __nv_bfloat16* __restrict__ lo, int n4)
{
    int i = blockIdx.x * 256 + threadIdx.x;
    if (i >= n4) return;
    float4 v = ((const float4*)src)[i];
    __nv_bfloat16 h[4], l[4];
    float vv[4] = {v.x, v.y, v.z, v.w};
    #pragma unroll
    for (int j = 0; j < 4; j++) {
        h[j] = __float2bfloat16(vv[j]);
        l[j] = __float2bfloat16(vv[j] - __bfloat162float(h[j]));
    }
    ((uint2*)hi)[i] = *(uint2*)h;
    ((uint2*)lo)[i] = *(uint2*)l;
}

// ---------------------------------------------------------------------------
// Split-bf16 HMMA GEMM: C[M,N] = (Ah+Al)[M,K] @ (Bh+Bl)[N,K]^T + bias[N]
// (unchanged from R14; measured 177us on the big shape, tensor=48%)
// ---------------------------------------------------------------------------
__global__ void __launch_bounds__(256) gemm_mma_split(
    const __nv_bfloat16* __restrict__ Ah, const __nv_bfloat16* __restrict__ Al,
    const __nv_bfloat16* __restrict__ Bh, const __nv_bfloat16* __restrict__ Bl,
    const float* __restrict__ bias, float* __restrict__ C,
    int M, int N, int K)
{
    extern __shared__ __align__(16) uint32_t sm[];
    uint32_t* sA = sm;                 // [2 buf][2 mat][64 row][36 w]
    uint32_t* sB = sm + 9216;          // same

    const int tid   = threadIdx.x;
    const int wid   = tid >> 5;
    const int lane  = tid & 31;
    const int mBase = blockIdx.x * 64;
    const int nBase = blockIdx.y * 64;
    const int wm    = wid >> 2;        // 0..1
    const int wn    = wid & 3;         // 0..3
    const int lg    = lane >> 2;       // 0..7
    const int lc    = lane & 3;        // 0..3

    const uint32_t sA_sm = (uint32_t)__cvta_generic_to_shared(sA);
    const uint32_t sB_sm = (uint32_t)__cvta_generic_to_shared(sB);

    auto stage = [&](int c, int buf) {
        #pragma unroll
        for (int i = 0; i < 4; i++) {
            int L   = tid + i * 256;       // 0..1023
            int mat = L >> 9;
            int rem = L & 511;
            int row = rem >> 3;            // 0..63
            int seg = rem & 7;             // 16B segment
            const __nv_bfloat16* srcA =
                (mat ? Al : Ah) + (size_t)(mBase + row) * K + c * 64 + seg * 8;
            uint32_t dstA = sA_sm +
                (((buf * 2 + mat) * 64 + row) * 36 + seg * 4) * 4;
            asm volatile("cp.async.cg.shared.global [%0], [%1], 16;"
                         :: "r"(dstA), "l"(srcA));
            const __nv_bfloat16* srcB =
                (mat ? Bl : Bh) + (size_t)(nBase + row) * K + c * 64 + seg * 8;
            uint32_t dstB = sB_sm +
                (((buf * 2 + mat) * 64 + row) * 36 + seg * 4) * 4;
            asm volatile("cp.async.cg.shared.global [%0], [%1], 16;"
                         :: "r"(dstB), "l"(srcB));
        }
        asm volatile("cp.async.commit_group;");
    };

    float acc[2][2][4] = {};
    const int NC = K >> 6;

    stage(0, 0);

    for (int c = 0; c < NC; c++) {
        const int buf = c & 1;
        if (c + 1 < NC) {
            stage(c + 1, buf ^ 1);
            asm volatile("cp.async.wait_group 1;");
        } else {
            asm volatile("cp.async.wait_group 0;");
        }
        __syncthreads();

        const uint32_t* aH = sA + (buf * 2 + 0) * 2304;   // 64*36
        const uint32_t* aL = sA + (buf * 2 + 1) * 2304;
        const uint32_t* bH = sB + (buf * 2 + 0) * 2304;
        const uint32_t* bL = sB + (buf * 2 + 1) * 2304;

        #pragma unroll
        for (int s = 0; s < 4; s++) {
            const int w = s * 8 + lc;
            uint32_t ah[2][4], al[2][4], bh[2][2], bl[2][2];
            #pragma unroll
            for (int mt = 0; mt < 2; mt++) {
                const int r = wm * 32 + mt * 16 + lg;
                ah[mt][0] = aH[r * 36 + w];
                ah[mt][1] = aH[(r + 8) * 36 + w];
                ah[mt][2] = aH[r * 36 + w + 4];
                ah[mt][3] = aH[(r + 8) * 36 + w + 4];
                al[mt][0] = aL[r * 36 + w];
                al[mt][1] = aL[(r + 8) * 36 + w];
                al[mt][2] = aL[r * 36 + w + 4];
                al[mt][3] = aL[(r + 8) * 36 + w + 4];
            }
            #pragma unroll
            for (int nt = 0; nt < 2; nt++) {
                const int r = wn * 16 + nt * 8 + lg;
                bh[nt][0] = bH[r * 36 + w];
                bh[nt][1] = bH[r * 36 + w + 4];
                bl[nt][0] = bL[r * 36 + w];
                bl[nt][1] = bL[r * 36 + w + 4];
            }
            #pragma unroll
            for (int mt = 0; mt < 2; mt++)
                #pragma unroll
                for (int nt = 0; nt < 2; nt++) {
                    mma16816(acc[mt][nt], ah[mt][0], ah[mt][1], ah[mt][2],
                             ah[mt][3], bh[nt][0], bh[nt][1]);
                    mma16816(acc[mt][nt], ah[mt][0], ah[mt][1], ah[mt][2],
                             ah[mt][3], bl[nt][0], bl[nt][1]);
                    mma16816(acc[mt][nt], al[mt][0], al[mt][1], al[mt][2],
                             al[mt][3], bh[nt][0], bh[nt][1]);
                }
        }
        __syncthreads();
    }

    #pragma unroll
    for (int mt = 0; mt < 2; mt++) {
        #pragma unroll
        for (int nt = 0; nt < 2; nt++) {
            const int row = mBase + wm * 32 + mt * 16 + lg;
            const int col = nBase + wn * 16 + nt * 8 + lc * 2;
            const float b0 = __ldg(bias + col);
            const float b1 = __ldg(bias + col + 1);
            float* d = acc[mt][nt];
            *(float2*)&C[(size_t)row * N + col] =
                make_float2(d[0] + b0, d[1] + b1);
            *(float2*)&C[(size_t)(row + 8) * N + col] =
                make_float2(d[2] + b0, d[3] + b1);
        }
    }
}

// ---------------------------------------------------------------------------
// HMMA persistent recurrence, per-warp dataflow version.
// 128 CTAs: bq = bx>>5 (16 b-rows), jt = bx&31 (32 j-cols). 8 warps = 8-way
// k-split. Warp kq's k-range per half g is j in [g*512+kq*64, +64) -> exactly
// 2 producer CTAs per half. Each warp: acquire-polls its 4 producer flags,
// cp.asyncs its own warp-private 8KB hb slice (2 groups), wait_group +
// syncwarp only. CTA barriers remain solely around the cross-warp reduce.
// ---------------------------------------------------------------------------
__global__ void __launch_bounds__(REC_THREADS, 1) rnn_rec_mma(
    const float* __restrict__ pre,
    const float* __restrict__ h0,
    const float* __restrict__ wR,
    float* __restrict__ hid)
{
    extern __shared__ __align__(16) uint32_t smw[];
    uint32_t* wt  = smw + SM_WT;                  // [2][32][516]
    uint32_t* hb  = smw + SM_HB;                  // [2][16][516]
    float*    red = reinterpret_cast<float*>(smw + SM_RED);  // [8][16][36]

    const int tid   = threadIdx.x;
    const int wid   = tid >> 5;
    const int lane  = tid & 31;
    const int bx    = blockIdx.x;
    const int jt    = bx & 31;
    const int bq    = bx >> 5;
    const int jbase = jt * 32;
    const int bBase = bq * 16;

    // ---- Stage wR slice as bf16 hi/lo, layout [mat][n][k] ----
    {
        __nv_bfloat16* wb = reinterpret_cast<__nv_bfloat16*>(wt);
        for (int idx = tid; idx < 32 * HH; idx += REC_THREADS) {
            int n = idx & 31, k = idx >> 5;
            float v = wR[k * HH + jbase + n];
            __nv_bfloat16 hi = __float2bfloat16(v);
            __nv_bfloat16 lo = __float2bfloat16(v - __bfloat162float(hi));
            wb[(size_t)n * 1032 + k]        = hi;   // mat 0
            wb[(size_t)(32 + n) * 1032 + k] = lo;   // mat 1
        }
    }
    // ---- h0 -> history slot 0 (CTA 0 only) ----
    if (bx == 0) {
        for (int idx = tid; idx < BB * HH; idx += REC_THREADS) {
            float v = h0[idx & (HH - 1)];
            __nv_bfloat16 hi = __float2bfloat16(v);
            __nv_bfloat16 lo = __float2bfloat16(v - __bfloat162float(hi));
            g_hhh[idx] = hi;
            g_hhl[idx] = lo;
        }
    }
    if (tid == 0) g_flags[bx][0] = 0u;   // reset for graph replays
    grid_sync();

    const int kq = wid;                  // 0..7 k-split
    const int lg = lane >> 2;            // 0..7
    const int lc = lane & 3;             // 0..3

    const int ebl = tid >> 4;            // 0..15
    const int ejl = (tid & 15) * 2;      // 0,2,..,30
    const int eb  = bBase + ebl;

    unsigned* myFlag = &g_flags[bx][0];
    const uint32_t hb_sm = (uint32_t)__cvta_generic_to_shared(hb);

    // This warp's 4 producer flags (2 per half).
    const unsigned* fA0 = &g_flags[bq * 32 + 2 * kq][0];
    const unsigned* fA1 = &g_flags[bq * 32 + 2 * kq + 1][0];
    const unsigned* fB0 = &g_flags[bq * 32 + 16 + 2 * kq][0];
    const unsigned* fB1 = &g_flags[bq * 32 + 16 + 2 * kq + 1][0];

    for (int t = 0; t < TT; t++) {
        // Prefetch pre for this thread's outputs (DRAM latency hidden).
        const float* preRow = pre + ((size_t)t * BB + eb) * HH + jbase + ejl;
        float2 pv = __ldg((const float2*)preRow);

        const __nv_bfloat16* hxh = g_hhh + (size_t)t * (BB * HH) + bBase * HH;
        const __nv_bfloat16* hxl = g_hhl + (size_t)t * (BB * HH) + bBase * HH;

        // Stage this warp's slice of k-half g: 16 rows x 64 j x {hi,lo} = 4KB.
        auto stage_half = [&](int g) {
            #pragma unroll
            for (int i = 0; i < 8; i++) {
                int L   = lane + i * 32;           // 0..255
                int mat = L >> 7;                  // 0 hi, 1 lo
                int rem = L & 127;
                int row = rem >> 3;                // 0..15
                int seg = rem & 7;                 // 16B segment of 128B
                const __nv_bfloat16* src =
                    (mat ? hxl : hxh) + row * HH + g * 512 + kq * 64 + seg * 8;
                uint32_t dst = hb_sm +
                    (((mat * 16 + row) * 516 + g * 256 + kq * 32 + seg * 4) << 2);
                asm volatile("cp.async.cg.shared.global [%0], [%1], 16;"
                             :: "r"(dst), "l"(src));
            }
            asm volatile("cp.async.commit_group;");
        };

        // Wait for half-0 producers (every lane acquire-polls both flags),
        // stage half 0; then half-1 producers, stage half 1.
        if (t > 0) {
            unsigned c0, c1;
            do {
                asm volatile("ld.acquire.gpu.global.u32 %0, [%1];"
                             : "=r"(c0) : "l"(fA0) : "memory");
                asm volatile("ld.acquire.gpu.global.u32 %0, [%1];"
                             : "=r"(c1) : "l"(fA1) : "memory");
            } while ((int)c0 < t || (int)c1 < t);
        }
        stage_half(0);
        if (t > 0) {
            unsigned c0, c1;
            do {
                asm volatile("ld.acquire.gpu.global.u32 %0, [%1];"
                             : "=r"(c0) : "l"(fB0) : "memory");
                asm volatile("ld.acquire.gpu.global.u32 %0, [%1];"
                             : "=r"(c1) : "l"(fB1) : "memory");
            } while ((int)c0 < t || (int)c1 < t);
        }
        stage_half(1);

        float d[4][4] = {};

        const uint32_t* hbh = hb;
        const uint32_t* hbl = hb + 16 * 516;
        const uint32_t* wth = wt;
        const uint32_t* wtl = wt + 32 * 516;

        #pragma unroll
        for (int g = 0; g < 2; g++) {
            if (g == 0) asm volatile("cp.async.wait_group 1;");
            else        asm volatile("cp.async.wait_group 0;");
            __syncwarp();

            #pragma unroll
            for (int s = 0; s < 4; s++) {
                const int w = g * 256 + kq * 32 + s * 8 + lc;

                uint32_t a0h = hbh[lg * 516 + w];
                uint32_t a1h = hbh[(lg + 8) * 516 + w];
                uint32_t a2h = hbh[lg * 516 + w + 4];
                uint32_t a3h = hbh[(lg + 8) * 516 + w + 4];
                uint32_t a0l = hbl[lg * 516 + w];
                uint32_t a1l = hbl[(lg + 8) * 516 + w];
                uint32_t a2l = hbl[lg * 516 + w + 4];
                uint32_t a3l = hbl[(lg + 8) * 516 + w + 4];

                #pragma unroll
                for (int nt = 0; nt < 4; nt++) {
                    const int nr = nt * 8 + lg;
                    uint32_t b0h = wth[nr * 516 + w];
                    uint32_t b1h = wth[nr * 516 + w + 4];
                    uint32_t b0l = wtl[nr * 516 + w];
                    uint32_t b1l = wtl[nr * 516 + w + 4];
                    mma16816(d[nt], a0h, a1h, a2h, a3h, b0h, b1h);
                    mma16816(d[nt], a0h, a1h, a2h, a3h, b0l, b1l);
                    mma16816(d[nt], a0l, a1l, a2l, a3l, b0h, b1h);
                }
            }
        }

        // ---- write k-split partials to red ----
        {
            float* rp = red + wid * 576;
            #pragma unroll
            for (int nt = 0; nt < 4; nt++) {
                int col = nt * 8 + lc * 2;
                *(float2*)&rp[lg * 36 + col]       = make_float2(d[nt][0], d[nt][1]);
                *(float2*)&rp[(lg + 8) * 36 + col] = make_float2(d[nt][2], d[nt][3]);
            }
        }
        __syncthreads();

        // ---- epilogue: reduce 8 partials, +pre, tanh, publish ----
        float* hNew = hid + (size_t)t * (BB * HH);
        __nv_bfloat16* nxh = g_hhh + (size_t)(t + 1) * (BB * HH);
        __nv_bfloat16* nxl = g_hhl + (size_t)(t + 1) * (BB * HH);
        {
            float s0 = 0.f, s1 = 0.f;
            #pragma unroll
            for (int q = 0; q < 8; q++) {
                float2 p = *(float2*)&red[q * 576 + ebl * 36 + ejl];
                s0 += p.x; s1 += p.y;
            }
            float v0 = tanhf(pv.x + s0);
            float v1 = tanhf(pv.y + s1);

            *(float2*)&hNew[(size_t)eb * HH + jbase + ejl] = make_float2(v0, v1);

            __nv_bfloat16 h2[2], l2[2];
            h2[0] = __float2bfloat16(v0);
            h2[1] = __float2bfloat16(v1);
            l2[0] = __float2bfloat16(v0 - __bfloat162float(h2[0]));
            l2[1] = __float2bfloat16(v1 - __bfloat162float(h2[1]));
            *(uint32_t*)&nxh[(size_t)eb * HH + jbase + ejl] = *(uint32_t*)h2;
            *(uint32_t*)&nxl[(size_t)eb * HH + jbase + ejl] = *(uint32_t*)l2;
        }

        __threadfence();
        __syncthreads();
        if (tid == 0) {
            unsigned v = (unsigned)(t + 1);
            asm volatile("st.release.gpu.global.u32 [%0], %1;"
                         :: "l"(myFlag), "r"(v) : "memory");
        }
    }
}

// ---------------------------------------------------------------------------
// Launch: splits -> HMMA pre-GEMM -> persistent HMMA recurrence -> HMMA
// out-GEMM (out-GEMM reads the recurrent kernel's bf16 h history directly).
// ---------------------------------------------------------------------------
extern "C" void kernel_launch(void* const* d_in, const int* in_sizes, int n_in,
                              void* d_out, int out_size)
{
    const float* x  = (const float*)d_in[0];
    const float* h0 = (const float*)d_in[1];
    const float* wI = (const float*)d_in[2];
    const float* wR = (const float*)d_in[3];
    const float* wO = (const float*)d_in[4];
    const float* bR = (const float*)d_in[5];
    const float* bO = (const float*)d_in[6];

    float* outp = (float*)d_out;            // [T,B,O]
    float* hid  = outp + OUT_ELEMS;         // [T,B,H]

    float* pre = nullptr;
    cudaGetSymbolAddress((void**)&pre, g_pre);
    __nv_bfloat16 *xh, *xl, *wih, *wil, *woh, *wol, *hhh, *hhl;
    cudaGetSymbolAddress((void**)&xh,  g_xh);
    cudaGetSymbolAddress((void**)&xl,  g_xl);
    cudaGetSymbolAddress((void**)&wih, g_wih);
    cudaGetSymbolAddress((void**)&wil, g_wil);
    cudaGetSymbolAddress((void**)&woh, g_woh);
    cudaGetSymbolAddress((void**)&wol, g_wol);
    cudaGetSymbolAddress((void**)&hhh, g_hhh);
    cudaGetSymbolAddress((void**)&hhl, g_hhl);

    cudaFuncSetAttribute(rnn_rec_mma,
                         cudaFuncAttributeMaxDynamicSharedMemorySize,
                         REC_SMEM_BYTES);
    cudaFuncSetAttribute(gemm_mma_split,
                         cudaFuncAttributeMaxDynamicSharedMemorySize,
                         GEMM_SMEM_BYTES);

    // fp32 -> bf16 hi/lo splits
    split_kernel<<<(TT * BB * II / 4 + 255) / 256, 256>>>(x, xh, xl, TT * BB * II / 4);
    split_kernel<<<(HH * II / 4 + 255) / 256, 256>>>(wI, wih, wil, HH * II / 4);
    split_kernel<<<(OO * HH / 4 + 255) / 256, 256>>>(wO, woh, wol, OO * HH / 4);

    // pre[T*B, H] = x @ wI^T + bR   (HMMA split)
    gemm_mma_split<<<dim3(TT * BB / 64, HH / 64), 256, GEMM_SMEM_BYTES>>>(
        xh, xl, wih, wil, bR, pre, TT * BB, HH, II);

    // recurrence (writes hid fp32 + bf16 hi/lo history)
    rnn_rec_mma<<<REC_CTAS, REC_THREADS, REC_SMEM_BYTES>>>(pre, h0, wR, hid);

    // outputs[T*B, O] = hid @ wO^T + bO  (HMMA split, A = bf16 history slot 1+)
    gemm_mma_split<<<dim3(TT * BB / 64, OO / 64), 256, GEMM_SMEM_BYTES>>>(
        hhh + BB * HH, hhl + BB * HH, woh, wol, bO, outp, TT * BB, OO, HH);
}